// round 10
// baseline (speedup 1.0000x reference)
#include <cuda_runtime.h>

#define BB 2
#define CC 3
#define DD 128
#define HH 128
#define WW 128
#define NTASKS (BB * DD * HH)        // 32768 row tasks (b,d,h)
#define NTHREADS 128
#define WPB (NTHREADS / 32)
#define NBLOCKS (148 * 7)            // persistent, 7 blocks/SM (R7 operating point)
#define TOTW (NBLOCKS * WPB)

#define W_GRAD 0.1f
#define W_TV 0.002f
#define W_BG 0.15

// 9 partial sums: 0:m 1:mx 2:my 3:mz 4:(mae+mse) 5:bg 6:gtx 7:gty 8:gtz
#define NSUMS 9
__device__ double g_sums[NSUMS];
__device__ unsigned int g_count;

typedef unsigned long long u64;

// ---- packed f32x2 primitives (Blackwell FFMA2 path) ----
__device__ __forceinline__ u64 fma2(u64 a, u64 b, u64 c) {
    u64 d; asm("fma.rn.f32x2 %0,%1,%2,%3;" : "=l"(d) : "l"(a), "l"(b), "l"(c)); return d;
}
__device__ __forceinline__ u64 mul2(u64 a, u64 b) {
    u64 d; asm("mul.rn.f32x2 %0,%1,%2;" : "=l"(d) : "l"(a), "l"(b)); return d;
}
__device__ __forceinline__ u64 add2(u64 a, u64 b) {
    u64 d; asm("add.rn.f32x2 %0,%1,%2;" : "=l"(d) : "l"(a), "l"(b)); return d;
}
__device__ __forceinline__ u64 abs2(u64 a) { return a & 0x7FFFFFFF7FFFFFFFULL; }
__device__ __forceinline__ u64 pk2(float f) {
    u64 r; asm("mov.b64 %0,{%1,%1};" : "=l"(r) : "f"(f)); return r;
}
__device__ __forceinline__ float lo2(u64 v) { return __uint_as_float((unsigned)v); }
__device__ __forceinline__ float hi2(u64 v) { return __uint_as_float((unsigned)(v >> 32)); }
__device__ __forceinline__ float sum2(u64 v) { return lo2(v) + hi2(v); }

__device__ __forceinline__ float warp_sum(float v) {
#pragma unroll
    for (int o = 16; o; o >>= 1) v += __shfl_down_sync(0xffffffffu, v, o);
    return v;
}

__global__ __launch_bounds__(NTHREADS, 7)
void loss_kernel(const ulonglong2* __restrict__ pred,
                 const ulonglong2* __restrict__ targ,
                 const ulonglong2* __restrict__ mask,
                 float* __restrict__ out) {
    const int wid   = threadIdx.x >> 5;
    const int lane  = threadIdx.x & 31;
    const int gwarp = blockIdx.x * WPB + wid;

    const float ze = (lane < 31) ? 1.0f : 0.0f;       // w=127 edge
    const int ROWQ = WW / 4;                          // 32 x 16B per row
    const int CSTR = DD * HH * ROWQ;                  // channel stride

    const u64 NEG1 = pk2(-1.0f);
    const u64 ONE2 = pk2(1.0f);
    const u64 WG2  = pk2(W_GRAD);
    const u64 WTV2 = pk2(W_TV);

    u64 a_m = 0, a_mx = 0, a_my = 0, a_mm = 0, a_bg = 0, a_gtx = 0, a_gty = 0;
    float s_mz = 0.f, s_gtz = 0.f;

    // Grid-stride over independent (b,d,h) row tasks (interleaved ->
    // neighbor rows (h+1, d+1) run concurrently => L2 hits on reloads;
    // clamped neighbors make grad/TV terms self-zero so validity factors
    // are needed only on the mask counts).
    for (int task = gwarp; task < NTASKS; task += TOTW) {
        const int h = task & (HH - 1);
        const int d = (task >> 7) & (DD - 1);
        const int b = task >> 14;

        const int dskip = (d < DD - 1) ? HH * ROWQ : 0;
        const int hskip = (h < HH - 1) ? ROWQ : 0;

        const int mo = task * ROWQ + lane;
        const int po = mo + b * (CC - 1) * CSTR;

        const ulonglong2 M  = mask[mo];
        const ulonglong2 MD = mask[mo + dskip];
        const ulonglong2 MH = mask[mo + hskip];

        // binary masks: min(a,b) == a*b
        const u64 mx01 = mul2(M.x, MD.x), mx23 = mul2(M.y, MD.y);
        const u64 my01 = mul2(M.x, MH.x), my23 = mul2(M.y, MH.y);

        const float dv = (d < DD - 1) ? 1.0f : 0.0f;
        const float hv = (h < HH - 1) ? 1.0f : 0.0f;
        a_m  = add2(a_m, add2(M.x, M.y));
        a_mx = fma2(add2(mx01, mx23), pk2(dv), a_mx);
        a_my = fma2(add2(my01, my23), pk2(hv), a_my);

        const float m0 = lo2(M.x), m1 = hi2(M.x), m2 = lo2(M.y), m3 = hi2(M.y);
        const float mnx = __shfl_down_sync(0xffffffffu, m0, 1);
        const float mz0 = m0 * m1, mz1 = m1 * m2, mz2 = m2 * m3, mz3 = m3 * mnx * ze;
        s_mz += (mz0 + mz1) + (mz2 + mz3);

        const u64 inm01 = fma2(M.x, NEG1, ONE2);    // 1 - m
        const u64 inm23 = fma2(M.y, NEG1, ONE2);

#pragma unroll
        for (int c = 0; c < CC; c++) {
            const ulonglong2 P  = pred[po + c * CSTR];
            const ulonglong2 T  = targ[po + c * CSTR];
            const ulonglong2 PD = pred[po + c * CSTR + dskip];
            const ulonglong2 TD = targ[po + c * CSTR + dskip];
            const ulonglong2 PH = pred[po + c * CSTR + hskip];
            const ulonglong2 TH = targ[po + c * CSTR + hskip];

            const u64 df0  = fma2(T.x,  NEG1, P.x),  df1  = fma2(T.y,  NEG1, P.y);
            const u64 dfd0 = fma2(TD.x, NEG1, PD.x), dfd1 = fma2(TD.y, NEG1, PD.y);
            const u64 dfh0 = fma2(TH.x, NEG1, PH.x), dfh1 = fma2(TH.y, NEG1, PH.y);

            // (|df| + df^2) * m
            a_mm = fma2(fma2(df0, df0, abs2(df0)), M.x, a_mm);
            a_mm = fma2(fma2(df1, df1, abs2(df1)), M.y, a_mm);
            // |p| * (1-m)
            a_bg = fma2(abs2(P.x), inm01, a_bg);
            a_bg = fma2(abs2(P.y), inm23, a_bg);

            // x: (W_GRAD*|d(df)| + W_TV*|d(p)|) * min-mask
            a_gtx = fma2(fma2(abs2(fma2(P.x, NEG1, PD.x)), WTV2,
                              mul2(abs2(fma2(df0, NEG1, dfd0)), WG2)),
                         mx01, a_gtx);
            a_gtx = fma2(fma2(abs2(fma2(P.y, NEG1, PD.y)), WTV2,
                              mul2(abs2(fma2(df1, NEG1, dfd1)), WG2)),
                         mx23, a_gtx);
            // y
            a_gty = fma2(fma2(abs2(fma2(P.x, NEG1, PH.x)), WTV2,
                              mul2(abs2(fma2(df0, NEG1, dfh0)), WG2)),
                         my01, a_gty);
            a_gty = fma2(fma2(abs2(fma2(P.y, NEG1, PH.y)), WTV2,
                              mul2(abs2(fma2(df1, NEG1, dfh1)), WG2)),
                         my23, a_gty);

            // z (cross-lane): scalar
            const float p0 = lo2(P.x), p1 = hi2(P.x), p2 = lo2(P.y), p3 = hi2(P.y);
            const float d0 = lo2(df0), d1 = hi2(df0), d2 = lo2(df1), d3 = hi2(df1);
            const float dnx = __shfl_down_sync(0xffffffffu, d0, 1);
            const float pnx = __shfl_down_sync(0xffffffffu, p0, 1);
            s_gtz += fmaf(W_TV, fabsf(p1 - p0), W_GRAD * fabsf(d1 - d0)) * mz0
                   + fmaf(W_TV, fabsf(p2 - p1), W_GRAD * fabsf(d2 - d1)) * mz1
                   + fmaf(W_TV, fabsf(p3 - p2), W_GRAD * fabsf(d3 - d2)) * mz2
                   + fmaf(W_TV, fabsf(pnx - p3), W_GRAD * fabsf(dnx - d3)) * mz3;
        }
    }

    // ---- block-level reduction: warp -> smem -> NSUMS atomics per block ----
    __shared__ float red[WPB][NSUMS];
    float vals[NSUMS] = {sum2(a_m), sum2(a_mx), sum2(a_my), s_mz,
                         sum2(a_mm), sum2(a_bg), sum2(a_gtx), sum2(a_gty), s_gtz};
#pragma unroll
    for (int i = 0; i < NSUMS; i++) {
        const float r = warp_sum(vals[i]);
        if (lane == 0) red[wid][i] = r;
    }
    __syncthreads();

    if (threadIdx.x < NSUMS) {
        float acc = red[0][threadIdx.x];
#pragma unroll
        for (int w = 1; w < WPB; w++) acc += red[w][threadIdx.x];
        atomicAdd(&g_sums[threadIdx.x], (double)acc);
        __threadfence();
    }
    __syncthreads();

    // ---- last block finalizes + resets scratch (graph-replay determinism) ----
    if (threadIdx.x == 0) {
        const unsigned int old = atomicAdd(&g_count, 1u);
        if (old == NBLOCKS - 1) {
            double s[NSUMS];
#pragma unroll
            for (int i = 0; i < NSUMS; i++) s[i] = atomicAdd(&g_sums[i], 0.0);
            const double e = 1e-8;
            const double sm  = s[0], smx = s[1], smy = s[2], smz = s[3];
            const double mm  = s[4], bg  = s[5];
            const double gtx = s[6], gty = s[7], gtz = s[8];
            const double inv = (double)BB * DD * HH * WW - sm;

            const double r = mm / (sm * 3.0 + e)          // mae + mse
                           + gtx / (smx * 3.0 + e)
                           + gty / (smy * 3.0 + e)
                           + gtz / (smz * 3.0 + e)
                           + W_BG * (bg / (inv * 3.0 + e));
            out[0] = (float)r;

#pragma unroll
            for (int i = 0; i < NSUMS; i++) g_sums[i] = 0.0;
            g_count = 0u;
        }
    }
}

extern "C" void kernel_launch(void* const* d_in, const int* in_sizes, int n_in,
                              void* d_out, int out_size) {
    // mask is the smallest input; pred/target keep their relative order
    int mi = 0;
    for (int i = 1; i < n_in; i++)
        if (in_sizes[i] < in_sizes[mi]) mi = i;
    int others[2], k = 0;
    for (int i = 0; i < 3; i++)
        if (i != mi) others[k++] = i;

    const ulonglong2* pred = (const ulonglong2*)d_in[others[0]];
    const ulonglong2* targ = (const ulonglong2*)d_in[others[1]];
    const ulonglong2* mask = (const ulonglong2*)d_in[mi];

    loss_kernel<<<NBLOCKS, NTHREADS>>>(pred, targ, mask, (float*)d_out);
}